// round 15
// baseline (speedup 1.0000x reference)
#include <cuda_runtime.h>
#include <cstddef>

// CAN: per-sample 2-layer MLP, B=16384, N=50, D=16, fp32.
// x = relu(x @ W0 + b0); x = relu(x @ W1 + b1)
//
// R14: R10 skeleton (quad lane owns 10 rows x 4 cols, 20 lanes/sample,
// W staged via cp.async, in-place quad-private layer-0 writeback, direct
// STG.128 layer-1) with layer-0 reading x STRAIGHT FROM GLOBAL (quad lanes
// broadcast the same 64B row address). x smem holds only layer-0 output.

#define CAN_D 16
#define CAN_N 50
#define SPB 8                 // samples per block
#define TPB 160               // 8 samples * 20 lanes
#define XBLK 164              // floats per 10-row block (160 data + 4 pad)
#define X_STRIDE 820          // 5 blocks * 164 floats per sample
#define W_FLOATS 544
#define W_STRIDE 560          // mod 32 banks = 16 -> straddle-conflict-free

__device__ __forceinline__ void cp_async16(unsigned dst, const void* src) {
    asm volatile("cp.async.cg.shared.global [%0], [%1], 16;"
                 :: "r"(dst), "l"(src));
}

// One layer for lane's 10 rows x 4 cols, scalar FFMA, bias folded into d=0.
// wl: float4 view of layer params (W row d quarter ch at idx 4d+ch, bias
// quarter at 64+ch). xrow: lane's 10 rows (stride 16 floats) — may point
// at GLOBAL (layer 0) or SHARED (layer 1); both inlined so ptxas resolves
// the address space statically.
__device__ __forceinline__ void can_core(const float4* __restrict__ wl,
                                         const float* __restrict__ xrow,
                                         int ch, float acc[10][4])
{
    // ---- chunk 0 (d = 0..3), d=0 uses bias as FFMA addend ----
    {
        const float4 bv = wl[64 + ch];
        float4 w0 = wl[0 * 4 + ch];
        float4 w1 = wl[1 * 4 + ch];
        float4 w2 = wl[2 * 4 + ch];
        float4 w3 = wl[3 * 4 + ch];
        #pragma unroll
        for (int r = 0; r < 10; ++r) {
            float4 xv = *reinterpret_cast<const float4*>(xrow + r * 16);
            acc[r][0] = fmaf(xv.x, w0.x, bv.x);
            acc[r][1] = fmaf(xv.x, w0.y, bv.y);
            acc[r][2] = fmaf(xv.x, w0.z, bv.z);
            acc[r][3] = fmaf(xv.x, w0.w, bv.w);
            acc[r][0] = fmaf(xv.y, w1.x, acc[r][0]);
            acc[r][1] = fmaf(xv.y, w1.y, acc[r][1]);
            acc[r][2] = fmaf(xv.y, w1.z, acc[r][2]);
            acc[r][3] = fmaf(xv.y, w1.w, acc[r][3]);
            acc[r][0] = fmaf(xv.z, w2.x, acc[r][0]);
            acc[r][1] = fmaf(xv.z, w2.y, acc[r][1]);
            acc[r][2] = fmaf(xv.z, w2.z, acc[r][2]);
            acc[r][3] = fmaf(xv.z, w2.w, acc[r][3]);
            acc[r][0] = fmaf(xv.w, w3.x, acc[r][0]);
            acc[r][1] = fmaf(xv.w, w3.y, acc[r][1]);
            acc[r][2] = fmaf(xv.w, w3.z, acc[r][2]);
            acc[r][3] = fmaf(xv.w, w3.w, acc[r][3]);
        }
    }
    // ---- chunks 1..3 (d = 4..15) ----
    #pragma unroll
    for (int dc = 1; dc < 4; ++dc) {
        float4 w0 = wl[(4 * dc + 0) * 4 + ch];
        float4 w1 = wl[(4 * dc + 1) * 4 + ch];
        float4 w2 = wl[(4 * dc + 2) * 4 + ch];
        float4 w3 = wl[(4 * dc + 3) * 4 + ch];
        #pragma unroll
        for (int r = 0; r < 10; ++r) {
            float4 xv = *reinterpret_cast<const float4*>(xrow + r * 16 + 4 * dc);
            acc[r][0] = fmaf(xv.x, w0.x, acc[r][0]);
            acc[r][1] = fmaf(xv.x, w0.y, acc[r][1]);
            acc[r][2] = fmaf(xv.x, w0.z, acc[r][2]);
            acc[r][3] = fmaf(xv.x, w0.w, acc[r][3]);
            acc[r][0] = fmaf(xv.y, w1.x, acc[r][0]);
            acc[r][1] = fmaf(xv.y, w1.y, acc[r][1]);
            acc[r][2] = fmaf(xv.y, w1.z, acc[r][2]);
            acc[r][3] = fmaf(xv.y, w1.w, acc[r][3]);
            acc[r][0] = fmaf(xv.z, w2.x, acc[r][0]);
            acc[r][1] = fmaf(xv.z, w2.y, acc[r][1]);
            acc[r][2] = fmaf(xv.z, w2.z, acc[r][2]);
            acc[r][3] = fmaf(xv.z, w2.w, acc[r][3]);
            acc[r][0] = fmaf(xv.w, w3.x, acc[r][0]);
            acc[r][1] = fmaf(xv.w, w3.y, acc[r][1]);
            acc[r][2] = fmaf(xv.w, w3.z, acc[r][2]);
            acc[r][3] = fmaf(xv.w, w3.w, acc[r][3]);
        }
    }
}

__global__ __launch_bounds__(TPB, 5)
void can_kernel(const float* __restrict__ user,
                const float* __restrict__ item,
                float* __restrict__ out,
                int B)
{
    __shared__ __align__(16) float xs[SPB * X_STRIDE];   // 26.2 KB (L0 output)
    __shared__ __align__(16) float ws[SPB * W_STRIDE];   // 17.9 KB

    const int tid   = threadIdx.x;
    const int sbase = blockIdx.x * SPB;
    const int nsamp = min(SPB, B - sbase);
    const int nw4   = nsamp * 136;                        // <= 1088

    // ---- stage W only (2176B/sample) via cp.async ----
    {
        const float4* __restrict__ gw =
            reinterpret_cast<const float4*>(item + (size_t)sbase * W_FLOATS);
        #pragma unroll
        for (int k = 0; k < 7; ++k) {
            int i = tid + k * TPB;
            if (i < nw4) {
                int s = i / 136, f = i - s * 136;
                unsigned dst = (unsigned)__cvta_generic_to_shared(
                    ws + s * W_STRIDE + f * 4);
                cp_async16(dst, gw + i);
            }
        }
        asm volatile("cp.async.commit_group;" ::: "memory");
        asm volatile("cp.async.wait_group 0;"  ::: "memory");
    }
    __syncthreads();

    const int sl = tid / 20;        // local sample
    const int ls = tid - sl * 20;
    const int rg = ls >> 2;         // row group: rows rg*10 .. rg*10+9
    const int ch = ls & 3;          // column quarter: cols ch*4 .. ch*4+3

    if (sl < nsamp) {
        const float4* __restrict__ wl =
            reinterpret_cast<const float4*>(ws + sl * W_STRIDE);
        float* __restrict__ xrow = xs + sl * X_STRIDE + rg * XBLK;
        const float* __restrict__ gxrow =
            user + (size_t)(sbase + sl) * (CAN_N * CAN_D) + (rg * 10) * CAN_D;
        float acc[10][4];

        // ---- layer 0: x straight from GLOBAL (quad-broadcast LDG),
        //      relu, write own quarter to smem ----
        can_core(wl, gxrow, ch, acc);
        #pragma unroll
        for (int r = 0; r < 10; ++r) {
            *reinterpret_cast<float4*>(xrow + r * 16 + ch * 4) =
                make_float4(fmaxf(acc[r][0], 0.f), fmaxf(acc[r][1], 0.f),
                            fmaxf(acc[r][2], 0.f), fmaxf(acc[r][3], 0.f));
        }
        __syncwarp();               // quad writes visible before layer-1 reads

        // ---- layer 1: x from smem, relu, store straight to global ----
        can_core(wl + 68, xrow, ch, acc);   // layer-1 params at +272 floats
        float* __restrict__ gout = out + (size_t)(sbase + sl) * (CAN_N * CAN_D)
                                 + (rg * 10) * CAN_D + ch * 4;
        #pragma unroll
        for (int r = 0; r < 10; ++r) {
            *reinterpret_cast<float4*>(gout + r * CAN_D) =
                make_float4(fmaxf(acc[r][0], 0.f), fmaxf(acc[r][1], 0.f),
                            fmaxf(acc[r][2], 0.f), fmaxf(acc[r][3], 0.f));
        }
    }
}

extern "C" void kernel_launch(void* const* d_in, const int* in_sizes, int n_in,
                              void* d_out, int out_size)
{
    const float* user = (const float*)d_in[0];
    const float* item = (const float*)d_in[1];
    float* out = (float*)d_out;

    const int B = in_sizes[0] / (CAN_N * CAN_D);   // 16384
    const int grid = (B + SPB - 1) / SPB;

    can_kernel<<<grid, TPB>>>(user, item, out, B);
}

// round 16
// speedup vs baseline: 1.2583x; 1.2583x over previous
#include <cuda_runtime.h>
#include <cstddef>

// CAN: per-sample 2-layer MLP, B=16384, N=50, D=16, fp32.
// x = relu(x @ W0 + b0); x = relu(x @ W1 + b1)
//
// R15: R10 skeleton (quad lane owns 10 rows x 4 cols, cp.async staging,
// bias folded into d=0 FFMA, in-place quad-private layer-0) with the
// layer-1 STG.128 stores (12 cyc issue each) replaced by in-place STS.128
// (4 cyc) + 640B cp.async.bulk stores (engine-side, off the issue path).

#define CAN_D 16
#define CAN_N 50
#define SPB 8                 // samples per block
#define TPB 160               // 8 samples * 20 lanes
#define XBLK 164              // floats per 10-row block (160 data + 4 pad)
#define X_STRIDE 820          // 5 blocks * 164 floats per sample
#define W_FLOATS 544
#define W_STRIDE 560          // mod 32 banks = 16 -> straddle-conflict-free

__device__ __forceinline__ void cp_async16(unsigned dst, const void* src) {
    asm volatile("cp.async.cg.shared.global [%0], [%1], 16;"
                 :: "r"(dst), "l"(src));
}

// One layer for lane's 10 rows x 4 cols, scalar FFMA, bias folded into d=0.
// wl: float4 view of layer params (W row d quarter ch at idx 4d+ch, bias
// quarter at 64+ch). xrow: lane's 10 rows in smem, stride 16 floats.
__device__ __forceinline__ void can_core(const float4* __restrict__ wl,
                                         const float* __restrict__ xrow,
                                         int ch, float acc[10][4])
{
    // ---- chunk 0 (d = 0..3), d=0 uses bias as FFMA addend ----
    {
        const float4 bv = wl[64 + ch];
        float4 w0 = wl[0 * 4 + ch];
        float4 w1 = wl[1 * 4 + ch];
        float4 w2 = wl[2 * 4 + ch];
        float4 w3 = wl[3 * 4 + ch];
        #pragma unroll
        for (int r = 0; r < 10; ++r) {
            float4 xv = *reinterpret_cast<const float4*>(xrow + r * 16);
            acc[r][0] = fmaf(xv.x, w0.x, bv.x);
            acc[r][1] = fmaf(xv.x, w0.y, bv.y);
            acc[r][2] = fmaf(xv.x, w0.z, bv.z);
            acc[r][3] = fmaf(xv.x, w0.w, bv.w);
            acc[r][0] = fmaf(xv.y, w1.x, acc[r][0]);
            acc[r][1] = fmaf(xv.y, w1.y, acc[r][1]);
            acc[r][2] = fmaf(xv.y, w1.z, acc[r][2]);
            acc[r][3] = fmaf(xv.y, w1.w, acc[r][3]);
            acc[r][0] = fmaf(xv.z, w2.x, acc[r][0]);
            acc[r][1] = fmaf(xv.z, w2.y, acc[r][1]);
            acc[r][2] = fmaf(xv.z, w2.z, acc[r][2]);
            acc[r][3] = fmaf(xv.z, w2.w, acc[r][3]);
            acc[r][0] = fmaf(xv.w, w3.x, acc[r][0]);
            acc[r][1] = fmaf(xv.w, w3.y, acc[r][1]);
            acc[r][2] = fmaf(xv.w, w3.z, acc[r][2]);
            acc[r][3] = fmaf(xv.w, w3.w, acc[r][3]);
        }
    }
    // ---- chunks 1..3 (d = 4..15) ----
    #pragma unroll
    for (int dc = 1; dc < 4; ++dc) {
        float4 w0 = wl[(4 * dc + 0) * 4 + ch];
        float4 w1 = wl[(4 * dc + 1) * 4 + ch];
        float4 w2 = wl[(4 * dc + 2) * 4 + ch];
        float4 w3 = wl[(4 * dc + 3) * 4 + ch];
        #pragma unroll
        for (int r = 0; r < 10; ++r) {
            float4 xv = *reinterpret_cast<const float4*>(xrow + r * 16 + 4 * dc);
            acc[r][0] = fmaf(xv.x, w0.x, acc[r][0]);
            acc[r][1] = fmaf(xv.x, w0.y, acc[r][1]);
            acc[r][2] = fmaf(xv.x, w0.z, acc[r][2]);
            acc[r][3] = fmaf(xv.x, w0.w, acc[r][3]);
            acc[r][0] = fmaf(xv.y, w1.x, acc[r][0]);
            acc[r][1] = fmaf(xv.y, w1.y, acc[r][1]);
            acc[r][2] = fmaf(xv.y, w1.z, acc[r][2]);
            acc[r][3] = fmaf(xv.y, w1.w, acc[r][3]);
            acc[r][0] = fmaf(xv.z, w2.x, acc[r][0]);
            acc[r][1] = fmaf(xv.z, w2.y, acc[r][1]);
            acc[r][2] = fmaf(xv.z, w2.z, acc[r][2]);
            acc[r][3] = fmaf(xv.z, w2.w, acc[r][3]);
            acc[r][0] = fmaf(xv.w, w3.x, acc[r][0]);
            acc[r][1] = fmaf(xv.w, w3.y, acc[r][1]);
            acc[r][2] = fmaf(xv.w, w3.z, acc[r][2]);
            acc[r][3] = fmaf(xv.w, w3.w, acc[r][3]);
        }
    }
}

__global__ __launch_bounds__(TPB, 5)
void can_kernel(const float* __restrict__ user,
                const float* __restrict__ item,
                float* __restrict__ out,
                int B)
{
    __shared__ __align__(16) float xs[SPB * X_STRIDE];   // 26.2 KB
    __shared__ __align__(16) float ws[SPB * W_STRIDE];   // 17.9 KB

    const int tid   = threadIdx.x;
    const int sbase = blockIdx.x * SPB;
    const int nsamp = min(SPB, B - sbase);
    const int nf4   = nsamp * 200;                        // <= 1600
    const int nw4   = nsamp * 136;                        // <= 1088

    // ---- stage x and W via cp.async ----
    {
        const float4* __restrict__ gx =
            reinterpret_cast<const float4*>(user + (size_t)sbase * (CAN_N * CAN_D));
        #pragma unroll
        for (int k = 0; k < 10; ++k) {
            int i = tid + k * TPB;
            if (i < nf4) {
                int s = i / 200, f = i - s * 200;
                int row = f >> 2, q = f & 3;
                int rb = row / 10, rr = row - rb * 10;
                unsigned dst = (unsigned)__cvta_generic_to_shared(
                    xs + s * X_STRIDE + rb * XBLK + rr * 16 + q * 4);
                cp_async16(dst, gx + i);
            }
        }
        const float4* __restrict__ gw =
            reinterpret_cast<const float4*>(item + (size_t)sbase * W_FLOATS);
        #pragma unroll
        for (int k = 0; k < 7; ++k) {
            int i = tid + k * TPB;
            if (i < nw4) {
                int s = i / 136, f = i - s * 136;
                unsigned dst = (unsigned)__cvta_generic_to_shared(
                    ws + s * W_STRIDE + f * 4);
                cp_async16(dst, gw + i);
            }
        }
        asm volatile("cp.async.commit_group;" ::: "memory");
        asm volatile("cp.async.wait_group 0;"  ::: "memory");
    }
    __syncthreads();

    const int sl = tid / 20;        // local sample
    const int ls = tid - sl * 20;
    const int rg = ls >> 2;         // row group: rows rg*10 .. rg*10+9
    const int ch = ls & 3;          // column quarter: cols ch*4 .. ch*4+3

    if (sl < nsamp) {
        const float4* __restrict__ wl =
            reinterpret_cast<const float4*>(ws + sl * W_STRIDE);
        float* __restrict__ xrow = xs + sl * X_STRIDE + rg * XBLK;
        float acc[10][4];

        // ---- layer 0: accumulate, relu, write own quarter back in place ----
        can_core(wl, xrow, ch, acc);
        __syncwarp();               // quad finishes reading before overwrite
        #pragma unroll
        for (int r = 0; r < 10; ++r) {
            *reinterpret_cast<float4*>(xrow + r * 16 + ch * 4) =
                make_float4(fmaxf(acc[r][0], 0.f), fmaxf(acc[r][1], 0.f),
                            fmaxf(acc[r][2], 0.f), fmaxf(acc[r][3], 0.f));
        }
        __syncwarp();               // quad writes visible before layer-1 reads

        // ---- layer 1: accumulate, relu, write back in place (STS, 4cyc) ----
        can_core(wl + 68, xrow, ch, acc);   // layer-1 params at +272 floats
        __syncwarp();               // quad finishes layer-1 reads first
        #pragma unroll
        for (int r = 0; r < 10; ++r) {
            *reinterpret_cast<float4*>(xrow + r * 16 + ch * 4) =
                make_float4(fmaxf(acc[r][0], 0.f), fmaxf(acc[r][1], 0.f),
                            fmaxf(acc[r][2], 0.f), fmaxf(acc[r][3], 0.f));
        }
    }
    __syncthreads();

    // ---- bulk-store results: 5 x 640B per sample (engine-side) ----
    if (tid < nsamp * 5) {
        asm volatile("fence.proxy.async.shared::cta;" ::: "memory");
        int s = tid / 5, rb = tid - s * 5;
        unsigned src = (unsigned)__cvta_generic_to_shared(
            xs + s * X_STRIDE + rb * XBLK);
        float* dst = out + (size_t)(sbase + s) * (CAN_N * CAN_D) + rb * 160;
        asm volatile(
            "cp.async.bulk.global.shared::cta.bulk_group [%0], [%1], %2;"
            :: "l"(dst), "r"(src), "r"(640u) : "memory");
        asm volatile("cp.async.bulk.commit_group;" ::: "memory");
        asm volatile("cp.async.bulk.wait_group 0;" ::: "memory");
    }
}

extern "C" void kernel_launch(void* const* d_in, const int* in_sizes, int n_in,
                              void* d_out, int out_size)
{
    const float* user = (const float*)d_in[0];
    const float* item = (const float*)d_in[1];
    float* out = (float*)d_out;

    const int B = in_sizes[0] / (CAN_N * CAN_D);   // 16384
    const int grid = (B + SPB - 1) / SPB;

    can_kernel<<<grid, TPB>>>(user, item, out, B);
}